// round 1
// baseline (speedup 1.0000x reference)
#include <cuda_runtime.h>
#include <cuda_bf16.h>
#include <math.h>

// Problem constants
#define B_   8
#define C_   256
#define H_   64
#define W_   64
#define O_   256
#define KK_  9      // 3x3
#define HW_  (H_*W_)          // 4096
#define KDIM (C_*KK_)         // 2304

// Scratch (device globals: allocation-free per harness rules)
__device__ float g_offset[B_ * 18 * HW_];      // offset conv output (b,18,h,w)
__device__ float g_wT[KK_ * C_ * O_];          // w_dcn transposed to [k][c][o]

// ---------------------------------------------------------------------------
// Kernel 1: transpose w_dcn (O,C,3,3) -> wT[k][c][o]  (coalesced GEMM B reads)
// ---------------------------------------------------------------------------
__global__ void transpose_w_kernel(const float* __restrict__ w_dcn) {
    int idx = blockIdx.x * 256 + threadIdx.x;   // over O_*KDIM = 589824
    if (idx < O_ * KDIM) {
        int o = idx / KDIM;
        int r = idx % KDIM;
        int c = r / KK_;
        int k = r % KK_;
        g_wT[(k * C_ + c) * O_ + o] = w_dcn[idx];
    }
}

// ---------------------------------------------------------------------------
// Kernel 2: offset conv: g_offset[b,oc,h,w] = b_off[oc] + sum_{c,ky,kx} ...
// One block per (b,h). 256 threads: group g = tid/64 handles oc in {g,g+4,...}
// ---------------------------------------------------------------------------
__global__ __launch_bounds__(256) void offset_conv_kernel(
    const float* __restrict__ x, const float* __restrict__ w_off,
    const float* __restrict__ b_off) {
    __shared__ float xs[8 * 3 * 64];   // x[b, c0..c0+8, h-1..h+1, :]
    __shared__ float ws[18 * 72];      // w_off[:, c0..c0+8, :, :]

    int tid = threadIdx.x;
    int blk = blockIdx.x;
    int b = blk >> 6, h = blk & 63;
    int g = tid >> 6, w = tid & 63;
    int nacc = (g < 2) ? 5 : 4;

    float acc[5];
#pragma unroll
    for (int j = 0; j < 5; j++) {
        int oc = g + 4 * j;
        acc[j] = (oc < 18) ? b_off[oc] : 0.f;
    }

    const float* xb = x + (size_t)b * C_ * HW_;

    for (int c0 = 0; c0 < C_; c0 += 8) {
        // load x slab (rows h-1..h+1, 8 channels), zero outside
#pragma unroll
        for (int e = tid; e < 1536; e += 256) {
            int c = e / 192, r = e % 192;
            int ky = r >> 6, ww = r & 63;
            int hy = h - 1 + ky;
            xs[e] = (hy >= 0 && hy < H_) ? xb[(c0 + c) * HW_ + hy * W_ + ww] : 0.f;
        }
        // load weight slab: ws[oc][c*9+k]
#pragma unroll
        for (int e = tid; e < 1296; e += 256) {
            int oc = e / 72, r = e % 72;
            ws[e] = w_off[oc * KDIM + c0 * KK_ + r];
        }
        __syncthreads();

#pragma unroll
        for (int c = 0; c < 8; c++) {
#pragma unroll
            for (int ky = 0; ky < 3; ky++) {
#pragma unroll
                for (int kx = 0; kx < 3; kx++) {
                    int ww = w - 1 + kx;
                    float xv = (ww >= 0 && ww < W_) ? xs[(c * 3 + ky) * 64 + ww] : 0.f;
                    int kidx = ky * 3 + kx;
#pragma unroll
                    for (int j = 0; j < 5; j++) {
                        if (j < nacc)
                            acc[j] += xv * ws[(g + 4 * j) * 72 + c * 9 + kidx];
                    }
                }
            }
        }
        __syncthreads();
    }

    for (int j = 0; j < nacc; j++) {
        int oc = g + 4 * j;
        g_offset[((b * 18 + oc) * H_ + h) * W_ + w] = acc[j];
    }
}

// ---------------------------------------------------------------------------
// Kernel 3: fused bilinear-sample + GEMM.
// Block = one (b,h): BM=64 (all w), BN=256 (all o), BK=32 c-chunk, kk outer.
// 256 threads, 8x8 register tile each.
// ---------------------------------------------------------------------------
__global__ __launch_bounds__(256, 2) void dcn_fused_kernel(
    const float* __restrict__ x, float* __restrict__ out) {
    __shared__ float As[32][64];    // [c_in_chunk][m]   8 KB
    __shared__ float Bs[32][256];   // [c_in_chunk][o]  32 KB

    int tid = threadIdx.x;
    int mblk = blockIdx.x;                // 0..511
    int b = mblk >> 6, h = mblk & 63;

    int cc = tid >> 6;                    // 0..3: c-subgroup for A fill
    int m  = tid & 63;                    // w position for A fill
    int tn = tid & 31;                    // n-group (8 o each)
    int tm = tid >> 5;                    // m-group (8 w each)

    float acc[8][8];
#pragma unroll
    for (int i = 0; i < 8; i++)
#pragma unroll
        for (int j = 0; j < 8; j++) acc[i][j] = 0.f;

    const float* xb = x + (size_t)b * C_ * HW_;

    for (int kk = 0; kk < KK_; kk++) {
        int ky = kk / 3, kx = kk % 3;
        // bilinear metadata for (m, kk) — per-thread registers
        float offy = g_offset[((b * 18 + kk * 2 + 0) * H_ + h) * W_ + m];
        float offx = g_offset[((b * 18 + kk * 2 + 1) * H_ + h) * W_ + m];
        float sy = offy + (float)(h - 1 + ky);
        float sx = offx + (float)(m - 1 + kx);
        float fy0 = floorf(sy), fx0 = floorf(sx);
        float fy = sy - fy0, fx = sx - fx0;
        int iy = (int)fy0, ix = (int)fx0;

        int   ci[4];
        float cw[4];
#pragma unroll
        for (int corner = 0; corner < 4; corner++) {
            int dy = corner >> 1, dx = corner & 1;
            int yi = iy + dy, xi = ix + dx;
            bool valid = (yi >= 0 && yi < H_ && xi >= 0 && xi < W_);
            float wy = dy ? fy : (1.f - fy);
            float wx = dx ? fx : (1.f - fx);
            cw[corner] = valid ? (wy * wx) : 0.f;
            ci[corner] = valid ? (yi * W_ + xi) : 0;
        }

        for (int c0 = 0; c0 < C_; c0 += 32) {
            // --- fill Bs (coalesced from g_wT) ---
            float4* Bs4 = (float4*)(&Bs[0][0]);
            const float4* wT4 = (const float4*)(g_wT + (kk * C_ + c0) * O_);
#pragma unroll
            for (int q = 0; q < 8; q++) Bs4[tid + 256 * q] = wT4[tid + 256 * q];

            // --- fill As (bilinear gather; x is L2-resident) ---
#pragma unroll
            for (int i = 0; i < 8; i++) {
                int c = cc * 8 + i;
                const float* xc = xb + (c0 + c) * HW_;
                float v = cw[0] * __ldg(xc + ci[0]) + cw[1] * __ldg(xc + ci[1])
                        + cw[2] * __ldg(xc + ci[2]) + cw[3] * __ldg(xc + ci[3]);
                As[c][m] = v;
            }
            __syncthreads();

            // --- GEMM on the 32-deep chunk ---
#pragma unroll
            for (int kc = 0; kc < 32; kc++) {
                float a[8], bb[8];
                *(float4*)(a)     = *(const float4*)(&As[kc][tm * 8]);
                *(float4*)(a + 4) = *(const float4*)(&As[kc][tm * 8 + 4]);
                *(float4*)(bb)     = *(const float4*)(&Bs[kc][tn * 8]);
                *(float4*)(bb + 4) = *(const float4*)(&Bs[kc][tn * 8 + 4]);
#pragma unroll
                for (int i = 0; i < 8; i++)
#pragma unroll
                    for (int j = 0; j < 8; j++) acc[i][j] += a[i] * bb[j];
            }
            __syncthreads();
        }
    }

    // --- store: out[b, n, h, w] ---
#pragma unroll
    for (int j = 0; j < 8; j++) {
        int n = tn * 8 + j;
        float* op = out + (((size_t)b * O_ + n) * H_ + h) * W_ + tm * 8;
        float4 v0 = make_float4(acc[0][j], acc[1][j], acc[2][j], acc[3][j]);
        float4 v1 = make_float4(acc[4][j], acc[5][j], acc[6][j], acc[7][j]);
        *(float4*)(op)     = v0;
        *(float4*)(op + 4) = v1;
    }
}

// ---------------------------------------------------------------------------
// Launch
// ---------------------------------------------------------------------------
extern "C" void kernel_launch(void* const* d_in, const int* in_sizes, int n_in,
                              void* d_out, int out_size) {
    const float* x     = (const float*)d_in[0];   // (8,256,64,64)
    const float* w_off = (const float*)d_in[1];   // (18,256,3,3)
    const float* b_off = (const float*)d_in[2];   // (18,)
    const float* w_dcn = (const float*)d_in[3];   // (256,256,3,3)
    float* out = (float*)d_out;                   // (8,256,64,64)

    transpose_w_kernel<<<(O_ * KDIM + 255) / 256, 256>>>(w_dcn);
    offset_conv_kernel<<<B_ * H_, 256>>>(x, w_off, b_off);
    dcn_fused_kernel<<<B_ * H_, 256>>>(x, out);
}

// round 3
// speedup vs baseline: 1.9672x; 1.9672x over previous
#include <cuda_runtime.h>
#include <cuda_bf16.h>
#include <math.h>
#include <cstdint>

// Problem constants
#define B_   8
#define C_   256
#define H_   64
#define W_   64
#define O_   256
#define KK_  9
#define HW_  (H_*W_)          // 4096
#define KDIM (C_*KK_)         // 2304

#define NCHUNK 72             // 9 kk * 8 c-chunks of 32
#define CK     32             // K per chunk

// ---------------------------------------------------------------------------
// Scratch (device globals; allocation-free)
// ---------------------------------------------------------------------------
__device__ float g_offset[B_ * 18 * HW_];
// Pre-split B tiles: per chunk q: [32 k][256 n] bf16, hi and lo
__device__ __align__(16) __nv_bfloat16 g_Bhi[NCHUNK * CK * O_];
__device__ __align__(16) __nv_bfloat16 g_Blo[NCHUNK * CK * O_];

// ---------------------------------------------------------------------------
// helpers
// ---------------------------------------------------------------------------
__device__ __forceinline__ uint32_t smem_u32(const void* p) {
    uint32_t a;
    asm("{ .reg .u64 t; cvta.to.shared.u64 t, %1; cvt.u32.u64 %0, t; }" : "=r"(a) : "l"(p));
    return a;
}

#define LDSM_X4(r, addr) \
    asm volatile("ldmatrix.sync.aligned.m8n8.x4.shared.b16 {%0,%1,%2,%3}, [%4];" \
        : "=r"((r)[0]), "=r"((r)[1]), "=r"((r)[2]), "=r"((r)[3]) : "r"(addr))

#define LDSM_X4T(r, addr) \
    asm volatile("ldmatrix.sync.aligned.m8n8.x4.trans.shared.b16 {%0,%1,%2,%3}, [%4];" \
        : "=r"((r)[0]), "=r"((r)[1]), "=r"((r)[2]), "=r"((r)[3]) : "r"(addr))

#define MMA16816(d, a, b0, b1) \
    asm volatile("mma.sync.aligned.m16n8k16.row.col.f32.bf16.bf16.f32 " \
        "{%0,%1,%2,%3}, {%4,%5,%6,%7}, {%8,%9}, {%0,%1,%2,%3};" \
        : "+f"((d)[0]), "+f"((d)[1]), "+f"((d)[2]), "+f"((d)[3]) \
        : "r"((a)[0]), "r"((a)[1]), "r"((a)[2]), "r"((a)[3]), "r"(b0), "r"(b1))

// ---------------------------------------------------------------------------
// Kernel 1: split w_dcn (O,C,3,3) into per-chunk bf16 hi/lo B tiles [32k][256n]
// thread per (o, c): reads 9 contiguous floats, writes 9 scattered bf16 pairs
// ---------------------------------------------------------------------------
__global__ void prep_b_kernel(const float* __restrict__ w_dcn) {
    int idx = blockIdx.x * 256 + threadIdx.x;   // 65536 = O_*C_
    if (idx >= O_ * C_) return;
    int o = idx >> 8, c = idx & 255;
    int cb = c >> 5, k = c & 31;
    const float* src = w_dcn + ((size_t)o * C_ + c) * KK_;
#pragma unroll
    for (int kk = 0; kk < KK_; kk++) {
        float v = src[kk];
        __nv_bfloat16 hi = __float2bfloat16(v);
        __nv_bfloat16 lo = __float2bfloat16(v - __bfloat162float(hi));
        uint32_t off = (uint32_t)(kk * 8 + cb) * (CK * O_) + k * O_ + o;
        g_Bhi[off] = hi;
        g_Blo[off] = lo;
    }
}

// ---------------------------------------------------------------------------
// Kernel 2: offset conv (unchanged; known correct)
// ---------------------------------------------------------------------------
__global__ __launch_bounds__(256) void offset_conv_kernel(
    const float* __restrict__ x, const float* __restrict__ w_off,
    const float* __restrict__ b_off) {
    __shared__ float xs[8 * 3 * 64];
    __shared__ float ws[18 * 72];

    int tid = threadIdx.x;
    int blk = blockIdx.x;
    int b = blk >> 6, h = blk & 63;
    int g = tid >> 6, w = tid & 63;
    int nacc = (g < 2) ? 5 : 4;

    float acc[5];
#pragma unroll
    for (int j = 0; j < 5; j++) {
        int oc = g + 4 * j;
        acc[j] = (oc < 18) ? b_off[oc] : 0.f;
    }

    const float* xb = x + (size_t)b * C_ * HW_;

    for (int c0 = 0; c0 < C_; c0 += 8) {
#pragma unroll
        for (int e = tid; e < 1536; e += 256) {
            int c = e / 192, r = e % 192;
            int ky = r >> 6, ww = r & 63;
            int hy = h - 1 + ky;
            xs[e] = (hy >= 0 && hy < H_) ? xb[(c0 + c) * HW_ + hy * W_ + ww] : 0.f;
        }
#pragma unroll
        for (int e = tid; e < 1296; e += 256) {
            int oc = e / 72, r = e % 72;
            ws[e] = w_off[oc * KDIM + c0 * KK_ + r];
        }
        __syncthreads();

#pragma unroll
        for (int c = 0; c < 8; c++) {
#pragma unroll
            for (int ky = 0; ky < 3; ky++) {
#pragma unroll
                for (int kx = 0; kx < 3; kx++) {
                    int ww = w - 1 + kx;
                    float xv = (ww >= 0 && ww < W_) ? xs[(c * 3 + ky) * 64 + ww] : 0.f;
                    int kidx = ky * 3 + kx;
#pragma unroll
                    for (int j = 0; j < 5; j++) {
                        if (j < nacc)
                            acc[j] += xv * ws[(g + 4 * j) * 72 + c * 9 + kidx];
                    }
                }
            }
        }
        __syncthreads();
    }

    for (int j = 0; j < nacc; j++) {
        int oc = g + 4 * j;
        g_offset[((b * 18 + oc) * H_ + h) * W_ + w] = acc[j];
    }
}

// ---------------------------------------------------------------------------
// Kernel 3: fused bilinear sample + mma.sync bf16-split GEMM
// CTA = one (b,h): M=64 (w), N=256 (o). 256 threads = 8 warps (2 M x 4 N),
// warp tile 32x64. K chunks of 32 over kk(9) x cb(8).
//
// smem (static, 44,032 B):
//   As_hi [64][40] bf16  @     0  (5120 B)
//   As_lo [64][40] bf16  @  5120  (5120 B)
//   Bs_hi [32][264] bf16 @ 10240  (16896 B)
//   Bs_lo [32][264] bf16 @ 27136  (16896 B)
//   epilogue buf float[128][66] reuses @10240 (33792 B)
// ---------------------------------------------------------------------------
#define A_STRIDE 40
#define B_STRIDE 264
#define SM_ALO   5120
#define SM_B     10240
#define SM_BLO_REL 16896

__global__ __launch_bounds__(256, 2) void dcn_mma_kernel(
    const float* __restrict__ x, float* __restrict__ out) {
    __shared__ __align__(16) char sm[44032];
    __nv_bfloat16 (*As_hi)[A_STRIDE] = (__nv_bfloat16(*)[A_STRIDE])(sm);
    __nv_bfloat16 (*As_lo)[A_STRIDE] = (__nv_bfloat16(*)[A_STRIDE])(sm + SM_ALO);
    __nv_bfloat16 (*Bs_hi)[B_STRIDE] = (__nv_bfloat16(*)[B_STRIDE])(sm + SM_B);
    __nv_bfloat16 (*Bs_lo)[B_STRIDE] = (__nv_bfloat16(*)[B_STRIDE])(sm + SM_B + SM_BLO_REL);

    int tid  = threadIdx.x;
    int lane = tid & 31;
    int wid  = tid >> 5;
    int wm = wid >> 2, wn = wid & 3;
    int m0 = wm * 32, n0 = wn * 64;

    int blk = blockIdx.x;
    int b = blk >> 6, h = blk & 63;
    const float* xb = x + (size_t)b * C_ * HW_;

    // A-build mapping
    int m  = tid & 63;          // w position
    int cg = tid >> 6;          // channel group (8 channels)

    // ldmatrix base addresses
    uint32_t aHi = smem_u32(sm) +
        (uint32_t)(((m0 + (lane & 15)) * A_STRIDE + ((lane >> 4) * 8)) * 2);
    uint32_t bHi = smem_u32(sm) + SM_B +
        (uint32_t)(((((lane & 7) + 8 * ((lane >> 3) & 1)) * B_STRIDE) + n0 + 8 * (lane >> 4)) * 2);

    float d[2][8][4];
#pragma unroll
    for (int i = 0; i < 2; i++)
#pragma unroll
        for (int j = 0; j < 8; j++)
#pragma unroll
            for (int k = 0; k < 4; k++) d[i][j][k] = 0.f;

#pragma unroll 1
    for (int kk = 0; kk < KK_; kk++) {
        int ky = kk / 3, kx = kk % 3;
        // bilinear metadata for (m, kk)
        float offy = g_offset[((b * 18 + kk * 2 + 0) * H_ + h) * W_ + m];
        float offx = g_offset[((b * 18 + kk * 2 + 1) * H_ + h) * W_ + m];
        float sy = offy + (float)(h - 1 + ky);
        float sx = offx + (float)(m - 1 + kx);
        float fy0 = floorf(sy), fx0 = floorf(sx);
        float fy = sy - fy0, fx = sx - fx0;
        int iy = (int)fy0, ix = (int)fx0;

        int   ci[4];
        float cw[4];
#pragma unroll
        for (int corner = 0; corner < 4; corner++) {
            int dy = corner >> 1, dx = corner & 1;
            int yi = iy + dy, xi = ix + dx;
            bool valid = (yi >= 0 && yi < H_ && xi >= 0 && xi < W_);
            float wy = dy ? fy : (1.f - fy);
            float wx = dx ? fx : (1.f - fx);
            cw[corner] = valid ? (wy * wx) : 0.f;
            ci[corner] = valid ? (yi * W_ + xi) : 0;
        }

#pragma unroll 1
        for (int cb = 0; cb < 8; cb++) {
            int q  = kk * 8 + cb;
            int c0 = cb * 32;

            // ---- B fill: coalesced float4 copies of pre-split chunk ----
            {
                const float4* sH = (const float4*)(g_Bhi + (size_t)q * (CK * O_));
                const float4* sL = (const float4*)(g_Blo + (size_t)q * (CK * O_));
#pragma unroll
                for (int i = 0; i < 4; i++) {
                    int e = tid + 256 * i;          // 1024 float4 = 32 rows x 32
                    int row = e >> 5, c4 = e & 31;
                    *(float4*)(&Bs_hi[row][c4 * 8]) = sH[e];
                    *(float4*)(&Bs_lo[row][c4 * 8]) = sL[e];
                }
            }

            // ---- A fill: 8 channels per thread, bilinear + bf16 split ----
#pragma unroll
            for (int p = 0; p < 4; p++) {
                int cl = cg * 8 + p * 2;
                const float* x0 = xb + (size_t)(c0 + cl) * HW_;
                const float* x1 = x0 + HW_;
                float v0 = cw[0] * __ldg(x0 + ci[0]) + cw[1] * __ldg(x0 + ci[1])
                         + cw[2] * __ldg(x0 + ci[2]) + cw[3] * __ldg(x0 + ci[3]);
                float v1 = cw[0] * __ldg(x1 + ci[0]) + cw[1] * __ldg(x1 + ci[1])
                         + cw[2] * __ldg(x1 + ci[2]) + cw[3] * __ldg(x1 + ci[3]);
                __nv_bfloat16 h0v = __float2bfloat16(v0);
                __nv_bfloat16 l0v = __float2bfloat16(v0 - __bfloat162float(h0v));
                __nv_bfloat16 h1v = __float2bfloat16(v1);
                __nv_bfloat16 l1v = __float2bfloat16(v1 - __bfloat162float(h1v));
                *(__nv_bfloat162*)(&As_hi[m][cl]) = __halves2bfloat162(h0v, h1v);
                *(__nv_bfloat162*)(&As_lo[m][cl]) = __halves2bfloat162(l0v, l1v);
            }

            __syncthreads();

            // ---- MMA: 2 k-steps of 16, 3 split terms each ----
#pragma unroll
            for (int ks = 0; ks < 2; ks++) {
                uint32_t a[2][4], bf[4][4];
                uint32_t aOff = (uint32_t)(ks * 32);               // 16 k * 2B
                uint32_t bOff = (uint32_t)(ks * 16 * B_STRIDE * 2);

                // HH
#pragma unroll
                for (int mt = 0; mt < 2; mt++) LDSM_X4(a[mt], aHi + aOff + mt * (16 * A_STRIDE * 2));
#pragma unroll
                for (int nq = 0; nq < 4; nq++) LDSM_X4T(bf[nq], bHi + bOff + nq * 32);
#pragma unroll
                for (int mt = 0; mt < 2; mt++)
#pragma unroll
                    for (int nt = 0; nt < 8; nt++)
                        MMA16816(d[mt][nt], a[mt], bf[nt >> 1][(nt & 1) * 2], bf[nt >> 1][(nt & 1) * 2 + 1]);

                // LH (A_lo x B_hi)
#pragma unroll
                for (int mt = 0; mt < 2; mt++) LDSM_X4(a[mt], aHi + SM_ALO + aOff + mt * (16 * A_STRIDE * 2));
#pragma unroll
                for (int mt = 0; mt < 2; mt++)
#pragma unroll
                    for (int nt = 0; nt < 8; nt++)
                        MMA16816(d[mt][nt], a[mt], bf[nt >> 1][(nt & 1) * 2], bf[nt >> 1][(nt & 1) * 2 + 1]);

                // HL (A_hi x B_lo)
#pragma unroll
                for (int mt = 0; mt < 2; mt++) LDSM_X4(a[mt], aHi + aOff + mt * (16 * A_STRIDE * 2));
#pragma unroll
                for (int nq = 0; nq < 4; nq++) LDSM_X4T(bf[nq], bHi + SM_BLO_REL + bOff + nq * 32);
#pragma unroll
                for (int mt = 0; mt < 2; mt++)
#pragma unroll
                    for (int nt = 0; nt < 8; nt++)
                        MMA16816(d[mt][nt], a[mt], bf[nt >> 1][(nt & 1) * 2], bf[nt >> 1][(nt & 1) * 2 + 1]);
            }

            __syncthreads();
        }
    }

    // ---- epilogue: smem transpose -> coalesced stores ----
    float (*buf)[66] = (float(*)[66])(sm + SM_B);   // 128 x 66 floats = 33792 B
#pragma unroll 1
    for (int pass = 0; pass < 2; pass++) {
        if ((wn >> 1) == pass) {
            int nb = n0 - pass * 128;
#pragma unroll
            for (int mt = 0; mt < 2; mt++)
#pragma unroll
                for (int nt = 0; nt < 8; nt++) {
                    int rrow = m0 + mt * 16 + (lane >> 2);
                    int ccol = nb + nt * 8 + 2 * (lane & 3);
                    buf[ccol][rrow]         = d[mt][nt][0];
                    buf[ccol + 1][rrow]     = d[mt][nt][1];
                    buf[ccol][rrow + 8]     = d[mt][nt][2];
                    buf[ccol + 1][rrow + 8] = d[mt][nt][3];
                }
        }
        __syncthreads();
        float* obase = out + ((size_t)b * O_ + pass * 128) * HW_ + h * 64;
#pragma unroll
        for (int i = 0; i < 16; i++) {
            int e = tid + 256 * i;        // 4096 float2 = 128 rows x 32
            int nl = e >> 5, c2 = e & 31;
            float2 v = *(float2*)(&buf[nl][c2 * 2]);
            *(float2*)(obase + (size_t)nl * HW_ + c2 * 2) = v;
        }
        __syncthreads();
    }
}

// ---------------------------------------------------------------------------
// Launch
// ---------------------------------------------------------------------------
extern "C" void kernel_launch(void* const* d_in, const int* in_sizes, int n_in,
                              void* d_out, int out_size) {
    const float* x     = (const float*)d_in[0];
    const float* w_off = (const float*)d_in[1];
    const float* b_off = (const float*)d_in[2];
    const float* w_dcn = (const float*)d_in[3];
    float* out = (float*)d_out;

    prep_b_kernel<<<(O_ * C_ + 255) / 256, 256>>>(w_dcn);
    offset_conv_kernel<<<B_ * H_, 256>>>(x, w_off, b_off);
    dcn_mma_kernel<<<B_ * H_, 256>>>(x, out);
}

// round 4
// speedup vs baseline: 3.2230x; 1.6384x over previous
#include <cuda_runtime.h>
#include <cuda_fp16.h>
#include <math.h>
#include <cstdint>

// Problem constants
#define B_   8
#define C_   256
#define H_   64
#define W_   64
#define O_   256
#define KK_  9
#define HW_  (H_*W_)          // 4096
#define KDIM (C_*KK_)         // 2304

#define CK     64             // K per chunk
#define NCH    36             // 9 kk * 4 c-chunks of 64

// ---------------------------------------------------------------------------
// Scratch (device globals; allocation-free)
// ---------------------------------------------------------------------------
__device__ float g_offset[B_ * 18 * HW_];
// Main-GEMM B (w_dcn) fp16 hi only: [36 chunk][64 k][256 n]
__device__ __align__(16) __half g_Bhi[NCH * CK * O_];
// Offset-conv B (w_off) fp16 hi/lo: [36 chunk][64 k][32 n(pad)]
__device__ __align__(16) __half g_WoffHi[NCH * CK * 32];
__device__ __align__(16) __half g_WoffLo[NCH * CK * 32];

// ---------------------------------------------------------------------------
// helpers
// ---------------------------------------------------------------------------
__device__ __forceinline__ uint32_t smem_u32(const void* p) {
    uint32_t a;
    asm("{ .reg .u64 t; cvta.to.shared.u64 t, %1; cvt.u32.u64 %0, t; }" : "=r"(a) : "l"(p));
    return a;
}

#define LDSM_X4(r, addr) \
    asm volatile("ldmatrix.sync.aligned.m8n8.x4.shared.b16 {%0,%1,%2,%3}, [%4];" \
        : "=r"((r)[0]), "=r"((r)[1]), "=r"((r)[2]), "=r"((r)[3]) : "r"(addr))

#define LDSM_X4T(r, addr) \
    asm volatile("ldmatrix.sync.aligned.m8n8.x4.trans.shared.b16 {%0,%1,%2,%3}, [%4];" \
        : "=r"((r)[0]), "=r"((r)[1]), "=r"((r)[2]), "=r"((r)[3]) : "r"(addr))

#define MMA16816(d, a, b0, b1) \
    asm volatile("mma.sync.aligned.m16n8k16.row.col.f32.f16.f16.f32 " \
        "{%0,%1,%2,%3}, {%4,%5,%6,%7}, {%8,%9}, {%0,%1,%2,%3};" \
        : "+f"((d)[0]), "+f"((d)[1]), "+f"((d)[2]), "+f"((d)[3]) \
        : "r"((a)[0]), "r"((a)[1]), "r"((a)[2]), "r"((a)[3]), "r"(b0), "r"(b1))

__device__ __forceinline__ __half2 split_hi2(float v0, float v1, __half2& lo2) {
    __half h0 = __float2half_rn(v0);
    __half h1 = __float2half_rn(v1);
    __half l0 = __float2half_rn(v0 - __half2float(h0));
    __half l1 = __float2half_rn(v1 - __half2float(h1));
    lo2 = __halves2half2(l0, l1);
    return __halves2half2(h0, h1);
}

// ---------------------------------------------------------------------------
// Kernel 1a: split w_dcn (O,C,3,3) -> g_Bhi [36][64][256] (fp16 hi only)
// ---------------------------------------------------------------------------
__global__ void prep_b_kernel(const float* __restrict__ w_dcn) {
    int idx = blockIdx.x * 256 + threadIdx.x;   // 65536 = O*C
    if (idx >= O_ * C_) return;
    int o = idx >> 8, c = idx & 255;
    int cb = c >> 6, k = c & 63;
    const float* src = w_dcn + ((size_t)o * C_ + c) * KK_;
#pragma unroll
    for (int kk = 0; kk < KK_; kk++) {
        g_Bhi[(size_t)(kk * 4 + cb) * (CK * O_) + k * O_ + o] = __float2half_rn(src[kk]);
    }
}

// ---------------------------------------------------------------------------
// Kernel 1b: split w_off (18,C,3,3) -> g_WoffHi/Lo [36][64][32] (n padded)
// ---------------------------------------------------------------------------
__global__ void prep_woff_kernel(const float* __restrict__ w_off) {
    int idx = blockIdx.x * 256 + threadIdx.x;   // 36*64*32 = 73728
    if (idx >= NCH * CK * 32) return;
    int q  = idx >> 11;          // chunk
    int r  = idx & 2047;
    int k  = r >> 5;
    int oc = r & 31;
    int kk = q >> 2, cb = q & 3;
    int c  = cb * 64 + k;
    float v = (oc < 18) ? w_off[((size_t)oc * C_ + c) * KK_ + kk] : 0.f;
    __half hi = __float2half_rn(v);
    __half lo = __float2half_rn(v - __half2float(hi));
    g_WoffHi[idx] = hi;
    g_WoffLo[idx] = lo;
}

// ---------------------------------------------------------------------------
// Kernel 2: offset conv via mma.sync (3-term fp16 split).
// CTA = (b, h-pair): M=128 (2 h rows x 64 w), N=32 (18 padded). 256 threads,
// 8 warps, warp tile 16m x 24n (3 n-tiles used).
// smem: AsHi[128][72] @0 (18432B), AsLo @18432, BsHi[64][40] @36864 (5120B),
//       BsLo @41984.  total 47104B.
// ---------------------------------------------------------------------------
#define OA_STR 72
#define OB_STR 40
#define OSM_ALO 18432
#define OSM_BHI 36864
#define OSM_BLO 41984

__global__ __launch_bounds__(256, 2) void offset_mma_kernel(
    const float* __restrict__ x, const float* __restrict__ b_off) {
    __shared__ __align__(16) char sm[47104];
    __half (*AsHi)[OA_STR] = (__half(*)[OA_STR])(sm);
    __half (*AsLo)[OA_STR] = (__half(*)[OA_STR])(sm + OSM_ALO);
    __half (*BsHi)[OB_STR] = (__half(*)[OB_STR])(sm + OSM_BHI);
    __half (*BsLo)[OB_STR] = (__half(*)[OB_STR])(sm + OSM_BLO);

    int tid = threadIdx.x, lane = tid & 31, wid = tid >> 5;
    int blk = blockIdx.x;
    int b = blk >> 5, h0 = (blk & 31) * 2;
    int m0 = wid * 16;

    int m  = tid & 127;
    int cg = tid >> 7;                 // 0..1: 32 channels each
    int hh = h0 + (m >> 6);
    int wp = m & 63;
    const float* xb = x + (size_t)b * C_ * HW_;

    uint32_t aHi = smem_u32(sm) +
        (uint32_t)(((m0 + (lane & 15)) * OA_STR + ((lane >> 4) * 8)) * 2);
    uint32_t bHi = smem_u32(sm) + OSM_BHI +
        (uint32_t)(((((lane & 7) + 8 * ((lane >> 3) & 1)) * OB_STR) + 8 * (lane >> 4)) * 2);

    float d[3][4];
#pragma unroll
    for (int i = 0; i < 3; i++)
#pragma unroll
        for (int j = 0; j < 4; j++) d[i][j] = 0.f;

#pragma unroll 1
    for (int kk = 0; kk < KK_; kk++) {
        int ky = kk / 3, kx = kk % 3;
        int hy = hh - 1 + ky;
        int wx = wp - 1 + kx;
        bool vr = (hy >= 0 && hy < H_ && wx >= 0 && wx < W_);
        const float* xrow = xb + hy * W_ + wx;    // + c*HW_

#pragma unroll 1
        for (int cb = 0; cb < 4; cb++) {
            int q  = kk * 4 + cb;
            int c0 = cb * 64;

            // B fill: 2048 halfs per array = 256 float4
            {
                const float4* sH = (const float4*)(g_WoffHi + (size_t)q * (CK * 32));
                const float4* sL = (const float4*)(g_WoffLo + (size_t)q * (CK * 32));
                int row = tid >> 2, c4 = tid & 3;
                *(float4*)(&BsHi[row][c4 * 8]) = sH[tid];
                *(float4*)(&BsLo[row][c4 * 8]) = sL[tid];
            }

            // A fill: 32 channels/thread, groups of 8 -> float4 stores
#pragma unroll
            for (int p = 0; p < 4; p++) {
                int cl = cg * 32 + 8 * p;
                __half2 hi[4], lo[4];
#pragma unroll
                for (int u = 0; u < 4; u++) {
                    int c = c0 + cl + 2 * u;
                    float v0 = vr ? __ldg(xrow + (size_t)c * HW_) : 0.f;
                    float v1 = vr ? __ldg(xrow + (size_t)(c + 1) * HW_) : 0.f;
                    hi[u] = split_hi2(v0, v1, lo[u]);
                }
                *(float4*)(&AsHi[m][cl]) = *(float4*)hi;
                *(float4*)(&AsLo[m][cl]) = *(float4*)lo;
            }
            __syncthreads();

#pragma unroll
            for (int ks = 0; ks < 4; ks++) {
                uint32_t a[4], bh[2][4], bl[2][4];
                uint32_t aOff = (uint32_t)(ks * 32);
                uint32_t bOff = (uint32_t)(ks * 16 * OB_STR * 2);
#pragma unroll
                for (int nq = 0; nq < 2; nq++) {
                    LDSM_X4T(bh[nq], bHi + bOff + nq * 32);
                    LDSM_X4T(bl[nq], bHi + (OSM_BLO - OSM_BHI) + bOff + nq * 32);
                }
                // Ah*Bh
                LDSM_X4(a, aHi + aOff);
#pragma unroll
                for (int nt = 0; nt < 3; nt++)
                    MMA16816(d[nt], a, bh[nt >> 1][(nt & 1) * 2], bh[nt >> 1][(nt & 1) * 2 + 1]);
                // Ah*Bl
#pragma unroll
                for (int nt = 0; nt < 3; nt++)
                    MMA16816(d[nt], a, bl[nt >> 1][(nt & 1) * 2], bl[nt >> 1][(nt & 1) * 2 + 1]);
                // Al*Bh
                LDSM_X4(a, aHi + OSM_ALO + aOff);
#pragma unroll
                for (int nt = 0; nt < 3; nt++)
                    MMA16816(d[nt], a, bh[nt >> 1][(nt & 1) * 2], bh[nt >> 1][(nt & 1) * 2 + 1]);
            }
            __syncthreads();
        }
    }

    // epilogue: direct scattered stores + bias
#pragma unroll
    for (int nt = 0; nt < 3; nt++)
#pragma unroll
        for (int r = 0; r < 4; r++) {
            int mm = m0 + (lane >> 2) + ((r >= 2) ? 8 : 0);
            int oc = nt * 8 + (lane & 3) * 2 + (r & 1);
            if (oc < 18) {
                g_offset[((b * 18 + oc) * H_ + h0 + (mm >> 6)) * W_ + (mm & 63)]
                    = d[nt][r] + __ldg(b_off + oc);
            }
        }
}

// ---------------------------------------------------------------------------
// Kernel 3: fused bilinear sample + mma.sync fp16 2-term GEMM
// CTA = one (b,h): M=64, N=256. 256 threads = 8 warps (2M x 4N), warp 32x64.
// 36 chunks of K=64.
// smem (dynamic 52224B): AsHi[64][72] @0 (9216), AsLo @9216,
//                        BsHi[64][264] @18432 (33792)
//   epilogue: float buf[128][66] (33792) reuses @0
// ---------------------------------------------------------------------------
#define A_STR 72
#define B_STR 264
#define SM_ALO 9216
#define SM_B   18432
#define SM_TOT 52224

__global__ __launch_bounds__(256, 2) void dcn_mma_kernel(
    const float* __restrict__ x, float* __restrict__ out) {
    extern __shared__ __align__(16) char sm[];
    __half (*AsHi)[A_STR] = (__half(*)[A_STR])(sm);
    __half (*AsLo)[A_STR] = (__half(*)[A_STR])(sm + SM_ALO);
    __half (*BsHi)[B_STR] = (__half(*)[B_STR])(sm + SM_B);

    int tid = threadIdx.x, lane = tid & 31, wid = tid >> 5;
    int wm = wid >> 2, wn = wid & 3;
    int m0 = wm * 32, n0 = wn * 64;

    int blk = blockIdx.x;
    int b = blk >> 6, h = blk & 63;
    const float* xb = x + (size_t)b * C_ * HW_;

    int m  = tid & 63;          // w position
    int cg = tid >> 6;          // 0..3: 16 channels each

    uint32_t aHi = smem_u32(sm) +
        (uint32_t)(((m0 + (lane & 15)) * A_STR + ((lane >> 4) * 8)) * 2);
    uint32_t bHi = smem_u32(sm) + SM_B +
        (uint32_t)(((((lane & 7) + 8 * ((lane >> 3) & 1)) * B_STR) + n0 + 8 * (lane >> 4)) * 2);

    float d[2][8][4];
#pragma unroll
    for (int i = 0; i < 2; i++)
#pragma unroll
        for (int j = 0; j < 8; j++)
#pragma unroll
            for (int k = 0; k < 4; k++) d[i][j][k] = 0.f;

#pragma unroll 1
    for (int kk = 0; kk < KK_; kk++) {
        int ky = kk / 3, kx = kk % 3;
        float offy = g_offset[((b * 18 + kk * 2 + 0) * H_ + h) * W_ + m];
        float offx = g_offset[((b * 18 + kk * 2 + 1) * H_ + h) * W_ + m];
        float sy = offy + (float)(h - 1 + ky);
        float sx = offx + (float)(m - 1 + kx);
        float fy0 = floorf(sy), fx0 = floorf(sx);
        float fy = sy - fy0, fx = sx - fx0;
        int iy = (int)fy0, ix = (int)fx0;

        int   ci[4];
        float cw[4];
#pragma unroll
        for (int corner = 0; corner < 4; corner++) {
            int dy = corner >> 1, dx = corner & 1;
            int yi = iy + dy, xi = ix + dx;
            bool valid = (yi >= 0 && yi < H_ && xi >= 0 && xi < W_);
            float wy = dy ? fy : (1.f - fy);
            float wx = dx ? fx : (1.f - fx);
            cw[corner] = valid ? (wy * wx) : 0.f;
            ci[corner] = valid ? (yi * W_ + xi) : 0;
        }

#pragma unroll 1
        for (int cb = 0; cb < 4; cb++) {
            int q  = kk * 4 + cb;
            int c0 = cb * 64;

            // B fill: 64x256 halfs = 2048 float4, coalesced
            {
                const float4* sH = (const float4*)(g_Bhi + (size_t)q * (CK * O_));
#pragma unroll
                for (int i = 0; i < 8; i++) {
                    int e = tid + 256 * i;
                    int row = e >> 5, c4 = e & 31;
                    *(float4*)(&BsHi[row][c4 * 8]) = sH[e];
                }
            }

            // A fill: 16 channels/thread, groups of 8 -> float4 stores
#pragma unroll
            for (int p = 0; p < 2; p++) {
                int cl = cg * 16 + 8 * p;
                __half2 hi[4], lo[4];
#pragma unroll
                for (int u = 0; u < 4; u++) {
                    const float* x0 = xb + (size_t)(c0 + cl + 2 * u) * HW_;
                    const float* x1 = x0 + HW_;
                    float v0 = cw[0] * __ldg(x0 + ci[0]) + cw[1] * __ldg(x0 + ci[1])
                             + cw[2] * __ldg(x0 + ci[2]) + cw[3] * __ldg(x0 + ci[3]);
                    float v1 = cw[0] * __ldg(x1 + ci[0]) + cw[1] * __ldg(x1 + ci[1])
                             + cw[2] * __ldg(x1 + ci[2]) + cw[3] * __ldg(x1 + ci[3]);
                    hi[u] = split_hi2(v0, v1, lo[u]);
                }
                *(float4*)(&AsHi[m][cl]) = *(float4*)hi;
                *(float4*)(&AsLo[m][cl]) = *(float4*)lo;
            }
            __syncthreads();

#pragma unroll
            for (int ks = 0; ks < 4; ks++) {
                uint32_t a[2][4], bf[4][4];
                uint32_t aOff = (uint32_t)(ks * 32);
                uint32_t bOff = (uint32_t)(ks * 16 * B_STR * 2);
#pragma unroll
                for (int nq = 0; nq < 4; nq++) LDSM_X4T(bf[nq], bHi + bOff + nq * 32);
                // Ah*Bh
#pragma unroll
                for (int mt = 0; mt < 2; mt++) LDSM_X4(a[mt], aHi + aOff + mt * (16 * A_STR * 2));
#pragma unroll
                for (int mt = 0; mt < 2; mt++)
#pragma unroll
                    for (int nt = 0; nt < 8; nt++)
                        MMA16816(d[mt][nt], a[mt], bf[nt >> 1][(nt & 1) * 2], bf[nt >> 1][(nt & 1) * 2 + 1]);
                // Al*Bh
#pragma unroll
                for (int mt = 0; mt < 2; mt++) LDSM_X4(a[mt], aHi + SM_ALO + aOff + mt * (16 * A_STR * 2));
#pragma unroll
                for (int mt = 0; mt < 2; mt++)
#pragma unroll
                    for (int nt = 0; nt < 8; nt++)
                        MMA16816(d[mt][nt], a[mt], bf[nt >> 1][(nt & 1) * 2], bf[nt >> 1][(nt & 1) * 2 + 1]);
            }
            __syncthreads();
        }
    }

    // epilogue: smem transpose -> coalesced stores
    float (*buf)[66] = (float(*)[66])(sm);
#pragma unroll 1
    for (int pass = 0; pass < 2; pass++) {
        if ((wn >> 1) == pass) {
            int nb = n0 - pass * 128;
#pragma unroll
            for (int mt = 0; mt < 2; mt++)
#pragma unroll
                for (int nt = 0; nt < 8; nt++) {
                    int rrow = m0 + mt * 16 + (lane >> 2);
                    int ccol = nb + nt * 8 + 2 * (lane & 3);
                    buf[ccol][rrow]         = d[mt][nt][0];
                    buf[ccol + 1][rrow]     = d[mt][nt][1];
                    buf[ccol][rrow + 8]     = d[mt][nt][2];
                    buf[ccol + 1][rrow + 8] = d[mt][nt][3];
                }
        }
        __syncthreads();
        float* obase = out + ((size_t)b * O_ + pass * 128) * HW_ + h * 64;
#pragma unroll
        for (int i = 0; i < 16; i++) {
            int e = tid + 256 * i;
            int nl = e >> 5, c2 = e & 31;
            float2 v = *(float2*)(&buf[nl][c2 * 2]);
            *(float2*)(obase + (size_t)nl * HW_ + c2 * 2) = v;
        }
        __syncthreads();
    }
}

// ---------------------------------------------------------------------------
// Launch
// ---------------------------------------------------------------------------
extern "C" void kernel_launch(void* const* d_in, const int* in_sizes, int n_in,
                              void* d_out, int out_size) {
    const float* x     = (const float*)d_in[0];
    const float* w_off = (const float*)d_in[1];
    const float* b_off = (const float*)d_in[2];
    const float* w_dcn = (const float*)d_in[3];
    float* out = (float*)d_out;

    static int inited = 0;
    if (!inited) {
        cudaFuncSetAttribute(dcn_mma_kernel,
                             cudaFuncAttributeMaxDynamicSharedMemorySize, SM_TOT);
        inited = 1;
    }

    prep_b_kernel<<<(O_ * C_ + 255) / 256, 256>>>(w_dcn);
    prep_woff_kernel<<<(NCH * CK * 32 + 255) / 256, 256>>>(w_off);
    offset_mma_kernel<<<B_ * H_ / 2, 256>>>(x, b_off);
    dcn_mma_kernel<<<B_ * H_, 256, SM_TOT>>>(x, out);
}